// round 11
// baseline (speedup 1.0000x reference)
#include <cuda_runtime.h>
#include <cstdint>

#define NCONV   8
#define HO      62
#define WO      62
#define NCOEF   8
#define INFEAT  9
#define NFEAT   9
#define BAND_R  8      // output rows per block
#define TROWS   10     // input rows per tile
#define TCOLS   68
#define PLANE   (TROWS * TCOLS)
#define NTHREADS 64

typedef unsigned long long u64;

__device__ __forceinline__ void fma2(u64 &d, u64 a, u64 b) {
    asm("fma.rn.f32x2 %0, %1, %2, %0;" : "+l"(d) : "l"(a), "l"(b));
}
__device__ __forceinline__ u64 dup2(float v) {
    u64 r; asm("mov.b64 %0, {%1, %1};" : "=l"(r) : "f"(v)); return r;
}
__device__ __forceinline__ float lo32(u64 a) { return __uint_as_float((unsigned)(a & 0xFFFFFFFFULL)); }
__device__ __forceinline__ float hi32(u64 a) { return __uint_as_float((unsigned)(a >> 32)); }

__global__ __launch_bounds__(NTHREADS, 9)
void kan_conv_kernel(const float* __restrict__ x,
                     const float* __restrict__ base_w,
                     const float* __restrict__ spline_w,
                     const float* __restrict__ spline_s,
                     const float* __restrict__ grid,
                     float* __restrict__ out) {
    __shared__ __align__(16) float s_feat[NFEAT * PLANE];       // 9*680*4 = 24480 B
    __shared__ __align__(16) float s_w[NFEAT * INFEAT * NCONV]; // 2592 B

    const int tid  = threadIdx.x;
    const int band = blockIdx.x;          // 0..7
    const int img  = blockIdx.y;          // 0..255
    const int y0   = band * BAND_R;

    // ---- Phase 0a: combined weights ----
    for (int idx = tid; idx < NFEAT * INFEAT * NCONV; idx += NTHREADS) {
        int f    = idx / (INFEAT * NCONV);
        int rest = idx % (INFEAT * NCONV);
        int i    = rest / NCONV;
        int n    = rest % NCONV;
        float v;
        if (f == 0) v = base_w[n * INFEAT + i];
        else        v = spline_w[(n * INFEAT + i) * NCOEF + (f - 1)] * spline_s[n * INFEAT + i];
        s_w[idx] = v;
    }

    // ---- Phase 0b: zero-fill the 8 basis planes ----
    {
        float4 z4 = make_float4(0.f, 0.f, 0.f, 0.f);
        float4* zp = (float4*)(s_feat + PLANE);
        #pragma unroll 4
        for (int i = tid; i < (8 * PLANE) / 4; i += NTHREADS)
            zp[i] = z4;
    }

    const float g0    = grid[0];
    const float inv_h = 1.0f / (grid[1] - grid[0]);
    __syncthreads();

    // ---- Phase 1: silu + 4 nonzero cubic B-spline bases ----
    const float* xin = x + img * 4096;
    #pragma unroll
    for (int e = tid; e < TROWS * 64; e += NTHREADS) {
        int row  = e >> 6;
        int col  = e & 63;
        int y_in = y0 + row;
        float v  = (y_in < 64) ? xin[y_in * 64 + col] : 0.0f;

        float* bp = &s_feat[row * TCOLS + col];
        float sig = 1.0f / (1.0f + __expf(-v));
        bp[0] = v * sig;

        float u  = (v - g0) * inv_h;
        float fj = floorf(u);
        int   j0 = (int)fj;
        float t  = u - fj;
        float t2 = t * t, t3 = t2 * t, om = 1.0f - t;
        const float s6 = 1.0f / 6.0f;
        float c0 = om * om * om * s6;
        float c1 = (3.0f * t3 - 6.0f * t2 + 4.0f) * s6;
        float c2 = (-3.0f * t3 + 3.0f * t2 + 3.0f * t + 1.0f) * s6;
        float c3 = t3 * s6;

        int jj;
        jj = j0 - 3; if (jj >= 0 && jj <= 7) bp[(1 + jj) * PLANE] = c0;
        jj = j0 - 2; if (jj >= 0 && jj <= 7) bp[(1 + jj) * PLANE] = c1;
        jj = j0 - 1; if (jj >= 0 && jj <= 7) bp[(1 + jj) * PLANE] = c2;
        jj = j0;     if (jj >= 0 && jj <= 7) bp[(1 + jj) * PLANE] = c3;
    }
    __syncthreads();

    // ---- Phase 2: 3x3 conv over 9 feature planes -> 8 outputs ----
    // thread -> row r (0..7), two 4-pixel groups at x0 and x0+32
    const int tx = tid & 7;           // 0..7
    const int r  = tid >> 3;          // 0..7
    const int x0 = tx * 4;            // 0..28 (left); right = x0+32
    const int y  = y0 + r;

    u64 accL[4][4];                   // [pixel][n-pair]
    u64 accR[4][4];
    #pragma unroll
    for (int p = 0; p < 4; ++p)
        #pragma unroll
        for (int q = 0; q < 4; ++q) { accL[p][q] = 0ULL; accR[p][q] = 0ULL; }

    const float* frow0 = &s_feat[r * TCOLS + x0];

    #pragma unroll
    for (int dy = 0; dy < 3; ++dy) {
        #pragma unroll
        for (int f = 0; f < NFEAT; ++f) {
            // hoist this iteration's 24 weight floats (broadcast LDS.128 x6)
            const float* wbase = &s_w[(f * INFEAT + dy * 3) * NCONV];
            ulonglong2 w0a = *(const ulonglong2*)(wbase);
            ulonglong2 w0b = *(const ulonglong2*)(wbase + 4);
            ulonglong2 w1a = *(const ulonglong2*)(wbase + 8);
            ulonglong2 w1b = *(const ulonglong2*)(wbase + 12);
            ulonglong2 w2a = *(const ulonglong2*)(wbase + 16);
            ulonglong2 w2b = *(const ulonglong2*)(wbase + 20);

            const float* fp = frow0 + (f * TROWS + dy) * TCOLS;

            // ---- left group ----
            {
                float4 v4 = *(const float4*)fp;
                float2 v2 = *(const float2*)(fp + 4);
                u64 dv[6];
                dv[0] = dup2(v4.x); dv[1] = dup2(v4.y); dv[2] = dup2(v4.z);
                dv[3] = dup2(v4.w); dv[4] = dup2(v2.x); dv[5] = dup2(v2.y);
                #pragma unroll
                for (int p = 0; p < 4; ++p) {
                    fma2(accL[p][0], dv[p],     w0a.x);
                    fma2(accL[p][1], dv[p],     w0a.y);
                    fma2(accL[p][2], dv[p],     w0b.x);
                    fma2(accL[p][3], dv[p],     w0b.y);
                    fma2(accL[p][0], dv[p + 1], w1a.x);
                    fma2(accL[p][1], dv[p + 1], w1a.y);
                    fma2(accL[p][2], dv[p + 1], w1b.x);
                    fma2(accL[p][3], dv[p + 1], w1b.y);
                    fma2(accL[p][0], dv[p + 2], w2a.x);
                    fma2(accL[p][1], dv[p + 2], w2a.y);
                    fma2(accL[p][2], dv[p + 2], w2b.x);
                    fma2(accL[p][3], dv[p + 2], w2b.y);
                }
            }
            // ---- right group (x0+32) ----
            {
                float4 v4 = *(const float4*)(fp + 32);
                float2 v2 = *(const float2*)(fp + 36);
                u64 dv[6];
                dv[0] = dup2(v4.x); dv[1] = dup2(v4.y); dv[2] = dup2(v4.z);
                dv[3] = dup2(v4.w); dv[4] = dup2(v2.x); dv[5] = dup2(v2.y);
                #pragma unroll
                for (int p = 0; p < 4; ++p) {
                    fma2(accR[p][0], dv[p],     w0a.x);
                    fma2(accR[p][1], dv[p],     w0a.y);
                    fma2(accR[p][2], dv[p],     w0b.x);
                    fma2(accR[p][3], dv[p],     w0b.y);
                    fma2(accR[p][0], dv[p + 1], w1a.x);
                    fma2(accR[p][1], dv[p + 1], w1a.y);
                    fma2(accR[p][2], dv[p + 1], w1b.x);
                    fma2(accR[p][3], dv[p + 1], w1b.y);
                    fma2(accR[p][0], dv[p + 2], w2a.x);
                    fma2(accR[p][1], dv[p + 2], w2a.y);
                    fma2(accR[p][2], dv[p + 2], w2b.x);
                    fma2(accR[p][3], dv[p + 2], w2b.y);
                }
            }
        }
    }

    // ---- store: out[((img*8 + n)*62 + y)*62 + x], STG.64 pairs ----
    if (y < HO) {
        #pragma unroll
        for (int q = 0; q < 4; ++q) {
            float* po_lo = out + ((img * NCONV + 2 * q    ) * HO + y) * WO;
            float* po_hi = out + ((img * NCONV + 2 * q + 1) * HO + y) * WO;
            // left: cols x0..x0+3, always < 32 -> valid
            *(float2*)(po_lo + x0)     = make_float2(lo32(accL[0][q]), lo32(accL[1][q]));
            *(float2*)(po_hi + x0)     = make_float2(hi32(accL[0][q]), hi32(accL[1][q]));
            *(float2*)(po_lo + x0 + 2) = make_float2(lo32(accL[2][q]), lo32(accL[3][q]));
            *(float2*)(po_hi + x0 + 2) = make_float2(hi32(accL[2][q]), hi32(accL[3][q]));
            // right: cols x0+32..x0+35; 62,63 invalid (tx==7 second pair)
            int xr = x0 + 32;
            *(float2*)(po_lo + xr)     = make_float2(lo32(accR[0][q]), lo32(accR[1][q]));
            *(float2*)(po_hi + xr)     = make_float2(hi32(accR[0][q]), hi32(accR[1][q]));
            if (xr + 2 < WO) {
                *(float2*)(po_lo + xr + 2) = make_float2(lo32(accR[2][q]), lo32(accR[3][q]));
                *(float2*)(po_hi + xr + 2) = make_float2(hi32(accR[2][q]), hi32(accR[3][q]));
            }
        }
    }
}

extern "C" void kernel_launch(void* const* d_in, const int* in_sizes, int n_in,
                              void* d_out, int out_size) {
    const float* x  = (const float*)d_in[0];
    const float* bw = (const float*)d_in[1];
    const float* sw = (const float*)d_in[2];
    const float* ss = (const float*)d_in[3];
    const float* gr = (const float*)d_in[4];
    float* out = (float*)d_out;

    dim3 grd(8, 256);   // 8 eight-row bands x 256 images
    kan_conv_kernel<<<grd, NTHREADS>>>(x, bw, sw, ss, gr, out);
}

// round 13
// speedup vs baseline: 1.2274x; 1.2274x over previous
#include <cuda_runtime.h>
#include <cstdint>

// Problem constants
#define BATCH   8
#define CHANS   32
#define HIN     64
#define WIN     64
#define HO      62
#define WO      62
#define NCONV   8
#define INFEAT  9      // 3x3
#define NCOEF   8      // grid 5 + order 3
#define NFEAT   9      // 1 silu + 8 basis
#define BAND_R  8      // output rows per block
#define TROWS   10     // input rows per tile (BAND_R + 2)
#define TCOLS   68     // padded tile width (64 data + 4 pad, keeps 16B align)
#define PLANE   (TROWS * TCOLS)
#define NTHREADS 128

typedef unsigned long long u64;

__device__ __forceinline__ void fma2(u64 &d, u64 a, u64 b) {
    asm("fma.rn.f32x2 %0, %1, %2, %0;" : "+l"(d) : "l"(a), "l"(b));
}
__device__ __forceinline__ u64 dup2(float v) {
    u64 r; asm("mov.b64 %0, {%1, %1};" : "=l"(r) : "f"(v)); return r;
}
__device__ __forceinline__ float lo32(u64 a) { return __uint_as_float((unsigned)(a & 0xFFFFFFFFULL)); }
__device__ __forceinline__ float hi32(u64 a) { return __uint_as_float((unsigned)(a >> 32)); }

__global__ __launch_bounds__(NTHREADS, 8)
void kan_conv_kernel(const float* __restrict__ x,
                     const float* __restrict__ base_w,
                     const float* __restrict__ spline_w,
                     const float* __restrict__ spline_s,
                     const float* __restrict__ grid,
                     float* __restrict__ out) {
    __shared__ __align__(16) float s_feat[NFEAT * PLANE];       // 24480 B
    __shared__ __align__(16) float s_w[NFEAT * INFEAT * NCONV]; // 2592 B

    const int tid  = threadIdx.x;
    const int band = blockIdx.x;          // 0..7
    const int img  = blockIdx.y;          // 0..255
    const int y0   = band * BAND_R;

    // ---- Phase 0a: combined weights ----
    for (int idx = tid; idx < NFEAT * INFEAT * NCONV; idx += NTHREADS) {
        int f    = idx / (INFEAT * NCONV);
        int rest = idx % (INFEAT * NCONV);
        int i    = rest / NCONV;
        int n    = rest % NCONV;
        float v;
        if (f == 0) v = base_w[n * INFEAT + i];
        else        v = spline_w[(n * INFEAT + i) * NCOEF + (f - 1)] * spline_s[n * INFEAT + i];
        s_w[idx] = v;
    }

    // ---- Phase 0b: vectorized zero-fill of the 8 basis planes ----
    {
        float4 z4 = make_float4(0.f, 0.f, 0.f, 0.f);
        float4* zp = (float4*)(s_feat + PLANE);
        #pragma unroll 4
        for (int i = tid; i < (8 * PLANE) / 4; i += NTHREADS)
            zp[i] = z4;
    }

    const float g0    = grid[0];
    const float inv_h = 1.0f / (grid[1] - grid[0]);
    __syncthreads();

    // ---- Phase 1: silu + 4 nonzero cubic B-spline bases ----
    const float* xin = x + img * (HIN * WIN);
    #pragma unroll
    for (int e = tid; e < TROWS * WIN; e += NTHREADS) {
        int row  = e >> 6;
        int col  = e & 63;
        int y_in = y0 + row;
        float v  = (y_in < HIN) ? xin[y_in * WIN + col] : 0.0f;

        float* bp = &s_feat[row * TCOLS + col];
        float sig = 1.0f / (1.0f + __expf(-v));
        bp[0] = v * sig;

        float u  = (v - g0) * inv_h;
        float fj = floorf(u);
        int   j0 = (int)fj;
        float t  = u - fj;
        float t2 = t * t, t3 = t2 * t, om = 1.0f - t;
        const float s6 = 1.0f / 6.0f;
        float c0 = om * om * om * s6;
        float c1 = (3.0f * t3 - 6.0f * t2 + 4.0f) * s6;
        float c2 = (-3.0f * t3 + 3.0f * t2 + 3.0f * t + 1.0f) * s6;
        float c3 = t3 * s6;

        int jj;
        jj = j0 - 3; if (jj >= 0 && jj <= 7) bp[(1 + jj) * PLANE] = c0;
        jj = j0 - 2; if (jj >= 0 && jj <= 7) bp[(1 + jj) * PLANE] = c1;
        jj = j0 - 1; if (jj >= 0 && jj <= 7) bp[(1 + jj) * PLANE] = c2;
        jj = j0;     if (jj >= 0 && jj <= 7) bp[(1 + jj) * PLANE] = c3;
    }
    __syncthreads();

    // ---- Phase 2: 3x3 conv over 9 feature planes -> 8 outputs, 4 px/thread ----
    const int txq = tid & 15;         // 0..15
    const int r   = tid >> 4;         // 0..7
    const int x0  = txq * 4;          // 0..60
    const int y   = y0 + r;

    u64 acc[4][4];                    // [pixel][n-pair]
    #pragma unroll
    for (int p = 0; p < 4; ++p)
        #pragma unroll
        for (int q = 0; q < 4; ++q) acc[p][q] = 0ULL;

    const float* frow0 = &s_feat[r * TCOLS + x0];

    // prefetch first iteration's features
    float4 va = *(const float4*)(frow0);
    float2 vb = *(const float2*)(frow0 + 4);

    #pragma unroll
    for (int it = 0; it < 27; ++it) {
        const int dy = it / 9, f = it % 9;

        // prefetch next iteration's feature window before this iteration's FMAs
        float4 na; float2 nb;
        if (it < 26) {
            const int it2 = it + 1;
            const float* np = frow0 + ((it2 % 9) * TROWS + (it2 / 9)) * TCOLS;
            na = *(const float4*)(np);
            nb = *(const float2*)(np + 4);
        }

        u64 dv[6];
        dv[0] = dup2(va.x); dv[1] = dup2(va.y); dv[2] = dup2(va.z);
        dv[3] = dup2(va.w); dv[4] = dup2(vb.x); dv[5] = dup2(vb.y);

        #pragma unroll
        for (int dx = 0; dx < 3; ++dx) {
            const float* wptr = &s_w[(f * INFEAT + dy * 3 + dx) * NCONV];
            ulonglong2 wa = *(const ulonglong2*)(wptr);
            ulonglong2 wb = *(const ulonglong2*)(wptr + 4);
            #pragma unroll
            for (int p = 0; p < 4; ++p) {
                u64 fd = dv[dx + p];
                fma2(acc[p][0], fd, wa.x);
                fma2(acc[p][1], fd, wa.y);
                fma2(acc[p][2], fd, wb.x);
                fma2(acc[p][3], fd, wb.y);
            }
        }
        va = na; vb = nb;
    }

    // ---- store: out[((img*8 + n)*62 + y)*62 + x], paired STG.64 ----
    if (y < HO) {
        #pragma unroll
        for (int q = 0; q < 4; ++q) {
            float* po_lo = out + ((img * NCONV + 2 * q    ) * HO + y) * WO + x0;
            float* po_hi = out + ((img * NCONV + 2 * q + 1) * HO + y) * WO + x0;
            *(float2*)po_lo = make_float2(lo32(acc[0][q]), lo32(acc[1][q]));
            *(float2*)po_hi = make_float2(hi32(acc[0][q]), hi32(acc[1][q]));
            if (x0 < 60) {
                *(float2*)(po_lo + 2) = make_float2(lo32(acc[2][q]), lo32(acc[3][q]));
                *(float2*)(po_hi + 2) = make_float2(hi32(acc[2][q]), hi32(acc[3][q]));
            }
        }
    }
}

extern "C" void kernel_launch(void* const* d_in, const int* in_sizes, int n_in,
                              void* d_out, int out_size) {
    const float* x  = (const float*)d_in[0];
    const float* bw = (const float*)d_in[1];
    const float* sw = (const float*)d_in[2];
    const float* ss = (const float*)d_in[3];
    const float* gr = (const float*)d_in[4];
    float* out = (float*)d_out;

    dim3 grd(8, BATCH * CHANS);   // 8 eight-row bands x 256 images
    kan_conv_kernel<<<grd, NTHREADS>>>(x, bw, sw, ss, gr, out);
}

// round 14
// speedup vs baseline: 1.3864x; 1.1295x over previous
#include <cuda_runtime.h>
#include <cuda_fp16.h>

typedef unsigned int u32;

#define NCONV 8
#define HO 62
#define WO 62
#define PX 48        // bytes per feature pixel (32 data + 16 pad -> conflict-free ldmatrix)
#define TROWS 10     // input rows per band tile

__device__ __forceinline__ u32 smem_u32(const void* p) {
    u32 a;
    asm("{ .reg .u64 t; cvta.to.shared.u64 t, %1; cvt.u32.u64 %0, t; }" : "=r"(a) : "l"(p));
    return a;
}
// pack two f32 -> f16x2 (first arg in low half) — validated R7-R9
__device__ __forceinline__ u32 pack_h2(float lo, float hi) {
    u32 r; asm("cvt.rn.f16x2.f32 %0, %1, %2;" : "=r"(r) : "f"(hi), "f"(lo)); return r;
}
__device__ __forceinline__ void ldsm_x4(u32 &r0, u32 &r1, u32 &r2, u32 &r3, u32 addr) {
    asm volatile("ldmatrix.sync.aligned.m8n8.x4.shared.b16 {%0,%1,%2,%3}, [%4];"
                 : "=r"(r0), "=r"(r1), "=r"(r2), "=r"(r3) : "r"(addr));
}
__device__ __forceinline__ void mma_k16(float c[4], u32 a0, u32 a1, u32 a2, u32 a3,
                                        u32 b0, u32 b1) {
    asm volatile(
        "mma.sync.aligned.m16n8k16.row.col.f32.f16.f16.f32 "
        "{%0,%1,%2,%3}, {%4,%5,%6,%7}, {%8,%9}, {%0,%1,%2,%3};"
        : "+f"(c[0]), "+f"(c[1]), "+f"(c[2]), "+f"(c[3])
        : "r"(a0), "r"(a1), "r"(a2), "r"(a3), "r"(b0), "r"(b1));
}

__global__ __launch_bounds__(128, 6)
void kan_hmma4(const float* __restrict__ x,
               const float* __restrict__ base_w,
               const float* __restrict__ spline_w,
               const float* __restrict__ spline_s,
               const float* __restrict__ grid_,
               float* __restrict__ out) {
    // feature tile: TROWS x 64 pixels, 16 fp16 (k16 vector) + 16B pad each
    __shared__ __align__(16) char   s_feat[TROWS * 64 * PX];   // 30720 B
    __shared__ __align__(16) __half s_bt[9 * 8 * 16];          // 2304 B [tap][n][k]

    const int tid  = threadIdx.x;
    const int w    = tid >> 5;
    const int lane = tid & 31;
    const int band = blockIdx.x;      // 0..7  (8 output rows; band 7 has 6)
    const int img  = blockIdx.y;      // 0..255
    const int y0   = band * 8;

    // ---- B staging (R8-validated fold): k0/k9=bw_hi, k1..8=spline, k10=bw_lo ----
    for (int idx = tid; idx < 9 * 8 * 16; idx += 128) {
        int tap = idx >> 7, rem = idx & 127, n = rem >> 4, k = rem & 15;
        __half hv = __float2half_rn(0.0f);
        if (k == 0 || k == 9) {
            hv = __float2half_rn(base_w[n * 9 + tap]);
        } else if (k <= 8) {
            hv = __float2half_rn(spline_w[(n * 9 + tap) * NCONV + (k - 1)]
                                 * spline_s[n * 9 + tap]);
        } else if (k == 10) {
            float bw = base_w[n * 9 + tap];
            hv = __float2half_rn(bw - __half2float(__float2half_rn(bw)));
        }
        s_bt[idx] = hv;
    }

    const float g0    = grid_[0];
    const float inv_h = 1.0f / (grid_[1] - grid_[0]);

    // ---- A-build: per pixel, k16 vec = [silu, b0..b7, slo, silu, 0x5] ----
    const float* xin = x + img * 4096;
    #pragma unroll
    for (int e = tid; e < TROWS * 64; e += 128) {   // 640 = 5 * 128
        int row = e >> 6, col = e & 63;
        int yin = y0 + row; if (yin > 63) yin = 63;  // band-7 clamp (outputs masked)
        float v = xin[yin * 64 + col];

        float sig  = 1.0f / (1.0f + __expf(-v));
        float silu = v * sig;
        float slo  = silu - __half2float(__float2half_rn(silu));

        float u  = (v - g0) * inv_h;
        float fj = floorf(u);
        int   j0 = (int)fj;
        float tt = u - fj;
        float t2 = tt * tt, t3 = t2 * tt, om = 1.0f - tt;
        const float s6 = 1.0f / 6.0f;
        float c0 = om * om * om * s6;
        float c1 = (3.0f * t3 - 6.0f * t2 + 4.0f) * s6;
        float c2 = (-3.0f * t3 + 3.0f * t2 + 3.0f * tt + 1.0f) * s6;
        float c3 = t3 * s6;
        int jb = j0 - 3;     // basis index of c0

        char* bp = s_feat + e * PX;
        // h0=silu, h1..7=0 ; h8=0, h9=slo, h10=silu, h11..15=0
        *(uint4*)bp        = make_uint4(pack_h2(silu, 0.0f), 0u, 0u, 0u);
        *(uint4*)(bp + 16) = make_uint4(pack_h2(0.0f, slo), pack_h2(silu, 0.0f), 0u, 0u);
        // basis slots h(1+jb+k) for k=0..3, guarded to 0<=jb+k<=7 (same as FFMA kernel)
        int jj;
        jj = jb;     if (jj >= 0 && jj <= 7) *(__half*)(bp + (1 + jj) * 2) = __float2half_rn(c0);
        jj = jb + 1; if (jj >= 0 && jj <= 7) *(__half*)(bp + (1 + jj) * 2) = __float2half_rn(c1);
        jj = jb + 2; if (jj >= 0 && jj <= 7) *(__half*)(bp + (1 + jj) * 2) = __float2half_rn(c2);
        jj = jb + 3; if (jj >= 0 && jj <= 7) *(__half*)(bp + (1 + jj) * 2) = __float2half_rn(c3);
    }
    __syncthreads();

    // ---- B fragments (k16 col layout; R8-validated addressing) ----
    u32 bf0[9], bf1[9];
    {
        const __half* bb = s_bt + (lane >> 2) * 16 + 2 * (lane & 3);
        #pragma unroll
        for (int tap = 0; tap < 9; ++tap) {
            bf0[tap] = *(const u32*)(bb + tap * 128);
            bf1[tap] = *(const u32*)(bb + tap * 128 + 8);
        }
    }

    // ---- tensor phase: warp w -> output rows y0+2w, y0+2w+1; 4 tiles/row ----
    // tile x-bases {0,16,32,46}: last overlaps so all pixels valid, no x-guards
    const u32 fb = smem_u32(s_feat);
    u32 ab[8];
    #pragma unroll
    for (int tau = 0; tau < 8; ++tau) {
        int r  = w * 2 + (tau >> 2);
        int xb = ((tau & 3) == 3) ? 46 : (tau & 3) * 16;
        ab[tau] = fb + (u32)((r * 64 + xb + (lane & 15)) * PX) + (u32)((lane >> 4) * 16);
    }

    float c[8][4];
    #pragma unroll
    for (int tau = 0; tau < 8; ++tau)
        #pragma unroll
        for (int i = 0; i < 4; ++i) c[tau][i] = 0.0f;

    #pragma unroll
    for (int tap = 0; tap < 9; ++tap) {
        const int dy = tap / 3, dx = tap % 3;
        const u32 off = (u32)((dy * 64 + dx) * PX);
        #pragma unroll
        for (int tau = 0; tau < 8; ++tau) {
            u32 a0, a1, a2, a3;
            ldsm_x4(a0, a1, a2, a3, ab[tau] + off);
            mma_k16(c[tau], a0, a1, a2, a3, bf0[tap], bf1[tap]);
        }
    }

    // ---- store: c rows = pixel x, c cols = conv n ----
    const int n0 = 2 * (lane & 3);
    #pragma unroll
    for (int tau = 0; tau < 8; ++tau) {
        int y = y0 + w * 2 + (tau >> 2);
        if (y < HO) {
            int xb = ((tau & 3) == 3) ? 46 : (tau & 3) * 16;
            #pragma unroll
            for (int g = 0; g < 2; ++g) {
                int xo = xb + g * 8 + (lane >> 2);        // <= 61 always
                float* p = out + ((img * NCONV + n0) * HO + y) * WO + xo;
                p[0]       = c[tau][g * 2 + 0];
                p[HO * WO] = c[tau][g * 2 + 1];
            }
        }
    }
}

extern "C" void kernel_launch(void* const* d_in, const int* in_sizes, int n_in,
                              void* d_out, int out_size) {
    const float* x  = (const float*)d_in[0];
    const float* bw = (const float*)d_in[1];
    const float* sw = (const float*)d_in[2];
    const float* ss = (const float*)d_in[3];
    const float* gr = (const float*)d_in[4];
    float* out = (float*)d_out;

    dim3 grd(8, 256);   // 8 eight-row bands x 256 images
    kan_hmma4<<<grd, 128>>>(x, bw, sw, ss, gr, out);
}